// round 2
// baseline (speedup 1.0000x reference)
#include <cuda_runtime.h>
#include <cstdint>
#include <stddef.h>

// Problem constants (match reference_code)
#define NN      16384
#define IN_DIM  64
#define L0      32
#define L1      48
#define L2      64
#define MLP_H   32
#define NCLS    2
#define CAPN    128   // max neighbors stored per row (Poisson(~33): P(deg>=128) ~ 1e-30)

// ---------------- scratch (__device__ globals; no allocation allowed) ----------
__device__ int   d_nbr[(size_t)NN * CAPN];   // 8 MB  ELL neighbor indices
__device__ int   d_cnt[NN];
__device__ float d_dinv[NN];
__device__ float d_xw[(size_t)NN * 64];      // 4 MB  dinv-scaled H@W
__device__ float d_hb[(size_t)NN * 64];      // 4 MB  layer activations
__device__ float d_part[128 * 64];           // column partial sums

// ---------------------------------------------------------------------------
// Kernel 1: stream 1 GiB dense adjacency once; build ELL lists + degrees.
// One warp per row (16384 floats = 4096 uint4 = 128 uint4/lane).
// HBM-bound: ~1 LDG.128 + ~4 ALU per 16 B; __ldcs keeps L2 clean for later tables.
// Deterministic ordering: fixed traversal + warp exclusive scan (no atomics).
// ---------------------------------------------------------------------------
__global__ __launch_bounds__(256) void build_sparse(const float* __restrict__ adj) {
    const int warp = blockIdx.x * 8 + (threadIdx.x >> 5);
    const int lane = threadIdx.x & 31;
    const int row  = warp;  // grid = 2048 blocks x 256 threads -> 16384 warps

    const uint4* __restrict__ arow =
        reinterpret_cast<const uint4*>(adj + (size_t)row * NN);

    int loc[32];
    int lc = 0;      // stored candidates (capped at 32)
    int cnt = 0;     // true nonzero count for this lane (uncapped)

    #pragma unroll 1
    for (int it = 0; it < 16; it++) {
        const int base = it * 256;
        uint4 v[8];
        #pragma unroll
        for (int u = 0; u < 8; u++)
            v[u] = __ldcs(&arow[base + u * 32 + lane]);   // streaming: read-once data
        unsigned o = 0u;
        #pragma unroll
        for (int u = 0; u < 8; u++)
            o |= (v[u].x | v[u].y | v[u].z | v[u].w);
        if (o) {  // ~6% of 128B lane-blocks contain a nonzero
            #pragma unroll
            for (int u = 0; u < 8; u++) {
                const int c = 4 * (base + u * 32 + lane);
                if (v[u].x) { if (lc < 32) loc[lc++] = c;     cnt++; }
                if (v[u].y) { if (lc < 32) loc[lc++] = c + 1; cnt++; }
                if (v[u].z) { if (lc < 32) loc[lc++] = c + 2; cnt++; }
                if (v[u].w) { if (lc < 32) loc[lc++] = c + 3; cnt++; }
            }
        }
    }
    const int stored = lc;

    // warp-wide exclusive scan of per-lane stored counts (deterministic order)
    const unsigned m = 0xffffffffu;
    int incl = stored;
    #pragma unroll
    for (int d = 1; d < 32; d <<= 1) {
        int nv = __shfl_up_sync(m, incl, d);
        if (lane >= d) incl += nv;
    }
    const int excl = incl - stored;

    // true degree (for dinv) via full reduction of cnt
    int deg = cnt;
    #pragma unroll
    for (int d = 16; d > 0; d >>= 1) deg += __shfl_xor_sync(m, deg, d);

    int* __restrict__ nl = d_nbr + (size_t)row * CAPN;
    for (int t = 0; t < stored; t++) {
        const int p = excl + t;
        if (p < CAPN) nl[p] = loc[t];
    }
    if (lane == 31) {
        const int tot = incl;  // total stored
        d_cnt[row] = tot < CAPN ? tot : CAPN;
    }
    if (lane == 0)
        d_dinv[row] = rsqrtf((float)deg + 1.0f);   // deg includes self loop, >= 1
}

// ---------------------------------------------------------------------------
// Kernel 2 (x3): XWs[i,j] = dinv[i] * sum_k H[i,k] * W[k,j]
// block(KO,4), 32 rows/block; W staged in shared; H row broadcast via uniform LDG.
// ---------------------------------------------------------------------------
template <int KI, int KO>
__global__ void gemm_scale(const float* __restrict__ H, const float* __restrict__ W,
                           const float* __restrict__ dinv, float* __restrict__ out) {
    __shared__ float Ws[KI * KO];
    const int tx = threadIdx.x;          // [0, KO)
    const int ty = threadIdx.y;          // [0, 4)
    const int tid = ty * KO + tx;
    for (int i = tid; i < KI * KO; i += KO * 4) Ws[i] = W[i];
    __syncthreads();

    const int row0 = blockIdx.x * 32;
    float acc[8];
    #pragma unroll
    for (int r = 0; r < 8; r++) acc[r] = 0.f;

    #pragma unroll
    for (int k = 0; k < KI; k++) {
        const float w = Ws[k * KO + tx];
        #pragma unroll
        for (int r = 0; r < 8; r++) {
            const int row = row0 + ty + 4 * r;
            acc[r] += __ldg(&H[(size_t)row * KI + k]) * w;
        }
    }
    #pragma unroll
    for (int r = 0; r < 8; r++) {
        const int row = row0 + ty + 4 * r;
        out[(size_t)row * KO + tx] = dinv[row] * acc[r];
    }
}

// ---------------------------------------------------------------------------
// Kernel 3 (x3): out[i,:] = relu( dinv[i]*(XWs[i,:] + sum_{j in nbr(i)} XWs[j,:]) + b )
// One warp per row; gathers hit the 4 MB XWs table resident in L2.
// ---------------------------------------------------------------------------
template <int KO>
__global__ __launch_bounds__(256) void spmm_relu(const float* __restrict__ XW,
                                                 const float* __restrict__ bias,
                                                 float* __restrict__ out) {
    const int warp = blockIdx.x * 8 + (threadIdx.x >> 5);
    const int lane = threadIdx.x & 31;
    const int row  = warp;

    float acc0 = XW[(size_t)row * KO + lane];       // self-loop term (dinv folded in)
    float acc1 = 0.f;
    const bool has1 = (KO > 32) && (lane + 32 < KO);
    if (has1) acc1 = XW[(size_t)row * KO + 32 + lane];

    const int n = d_cnt[row];
    const int* __restrict__ nl = d_nbr + (size_t)row * CAPN;

    for (int base = 0; base < n; base += 32) {
        int j_l = 0;
        if (base + lane < n) j_l = nl[base + lane];
        const int mlen = min(32, n - base);
        for (int k = 0; k < mlen; k++) {
            const int j = __shfl_sync(0xffffffffu, j_l, k);
            const float* __restrict__ xr = XW + (size_t)j * KO;
            acc0 += __ldg(&xr[lane]);
            if (has1) acc1 += __ldg(&xr[32 + lane]);
        }
    }

    const float di = d_dinv[row];
    out[(size_t)row * KO + lane] = fmaxf(di * acc0 + bias[lane], 0.f);
    if (has1)
        out[(size_t)row * KO + 32 + lane] = fmaxf(di * acc1 + bias[32 + lane], 0.f);
}

// ---------------------------------------------------------------------------
// Kernel 4: column partial sums of H3 (16384 x 64) -> 128 partials per column
// ---------------------------------------------------------------------------
__global__ void colsum(const float* __restrict__ H, float* __restrict__ part) {
    __shared__ float sh[4][64];
    const int col = threadIdx.x;   // 64
    const int ty  = threadIdx.y;   // 4
    const int row0 = blockIdx.x * 128;
    float s = 0.f;
    for (int r = ty; r < 128; r += 4)
        s += H[(size_t)(row0 + r) * 64 + col];
    sh[ty][col] = s;
    __syncthreads();
    if (ty == 0)
        part[blockIdx.x * 64 + col] = sh[0][col] + sh[1][col] + sh[2][col] + sh[3][col];
}

// ---------------------------------------------------------------------------
// Kernel 5: finish mean, MLP head (elu), logits, softmax. Single block, 64 thr.
// ---------------------------------------------------------------------------
__global__ void head(const float* __restrict__ part,
                     const float* __restrict__ Wh1, const float* __restrict__ bh1,
                     const float* __restrict__ Wh2, const float* __restrict__ bh2,
                     float* __restrict__ out) {
    __shared__ float g[64], h1[32], lg[2];
    const int t = threadIdx.x;  // 64 threads
    float s = 0.f;
    for (int b = 0; b < 128; b++) s += part[b * 64 + t];
    g[t] = s * (1.0f / (float)NN);
    __syncthreads();
    if (t < MLP_H) {
        float a = bh1[t];
        #pragma unroll
        for (int k = 0; k < 64; k++) a += g[k] * Wh1[k * MLP_H + t];
        h1[t] = (a > 0.f) ? a : expm1f(a);   // elu, alpha=1
    }
    __syncthreads();
    if (t < NCLS) {
        float a = bh2[t];
        #pragma unroll
        for (int k = 0; k < MLP_H; k++) a += h1[k] * Wh2[k * NCLS + t];
        lg[t] = a;
        out[t] = a;                          // logits
    }
    __syncthreads();
    if (t == 0) {
        const float mx = fmaxf(lg[0], lg[1]);
        const float e0 = expf(lg[0] - mx), e1 = expf(lg[1] - mx);
        const float inv = 1.f / (e0 + e1);
        out[2] = e0 * inv;                   // probs
        out[3] = e1 * inv;
    }
}

// ---------------------------------------------------------------------------
extern "C" void kernel_launch(void* const* d_in, const int* in_sizes, int n_in,
                              void* d_out, int out_size) {
    const float* nf   = (const float*)d_in[0];   // [N, 64]
    const float* adj  = (const float*)d_in[1];   // [N, N]
    const float* W0   = (const float*)d_in[2];   // [64, 32]
    const float* b0   = (const float*)d_in[3];
    const float* W1   = (const float*)d_in[4];   // [32, 48]
    const float* b1   = (const float*)d_in[5];
    const float* W2   = (const float*)d_in[6];   // [48, 64]
    const float* b2   = (const float*)d_in[7];
    const float* Wh1  = (const float*)d_in[8];   // [64, 32]
    const float* bh1  = (const float*)d_in[9];
    const float* Wh2  = (const float*)d_in[10];  // [32, 2]
    const float* bh2  = (const float*)d_in[11];
    float* out = (float*)d_out;

    // device-symbol addresses (host-side query; capture-safe, no stream ops)
    float *xw, *hb, *pt, *dinv;
    cudaGetSymbolAddress((void**)&xw,   d_xw);
    cudaGetSymbolAddress((void**)&hb,   d_hb);
    cudaGetSymbolAddress((void**)&pt,   d_part);
    cudaGetSymbolAddress((void**)&dinv, d_dinv);

    // 1) sparse extraction (the 1 GiB streaming pass; HBM-bound)
    build_sparse<<<NN / 8, 256>>>(adj);

    // 2) layer 1: 64 -> 32
    gemm_scale<IN_DIM, L0><<<NN / 32, dim3(L0, 4)>>>(nf, W0, dinv, xw);
    spmm_relu<L0><<<NN / 8, 256>>>(xw, b0, hb);

    // 3) layer 2: 32 -> 48
    gemm_scale<L0, L1><<<NN / 32, dim3(L1, 4)>>>(hb, W1, dinv, xw);
    spmm_relu<L1><<<NN / 8, 256>>>(xw, b1, hb);

    // 4) layer 3: 48 -> 64
    gemm_scale<L1, L2><<<NN / 32, dim3(L2, 4)>>>(hb, W2, dinv, xw);
    spmm_relu<L2><<<NN / 8, 256>>>(xw, b2, hb);

    // 5) mean-pool + MLP + softmax
    colsum<<<128, dim3(64, 4)>>>(hb, pt);
    head<<<1, 64>>>(pt, Wh1, bh1, Wh2, bh2, out);
}

// round 3
// speedup vs baseline: 1.0912x; 1.0912x over previous
#include <cuda_runtime.h>
#include <cstdint>
#include <stddef.h>

// Problem constants (match reference_code)
#define NN      16384
#define IN_DIM  64
#define L0      32
#define L1      48
#define L2      64
#define MLP_H   32
#define NCLS    2
#define CAPN    128   // max neighbors per row (Poisson(~33): P(deg>=128) ~ 1e-30)

// ---------------- scratch (__device__ globals; no allocation allowed) ----------
__device__ int   d_nbr[(size_t)NN * CAPN];   // 8 MB  ELL neighbor indices
__device__ int   d_cnt[NN];
__device__ float d_dinv[NN];
__device__ float d_xw[(size_t)NN * 64];      // 4 MB  dinv-scaled H@W
__device__ float d_hb[(size_t)NN * 64];      // 4 MB  layer activations
__device__ float d_part[128 * 64];           // column partial sums

// ---------------------------------------------------------------------------
// Kernel 1: stream 1 GiB dense adjacency once; build ELL lists + degrees.
// One warp per row. HBM-bound (~1 LDG.128 + ~4 ALU per 16 B). __ldcs streams.
// Deterministic ordering: fixed traversal + warp exclusive scan (no atomics).
// ---------------------------------------------------------------------------
__global__ __launch_bounds__(256) void build_sparse(const float* __restrict__ adj) {
    const int warp = blockIdx.x * 8 + (threadIdx.x >> 5);
    const int lane = threadIdx.x & 31;
    const int row  = warp;  // 2048 blocks x 8 warps -> 16384 rows

    const uint4* __restrict__ arow =
        reinterpret_cast<const uint4*>(adj + (size_t)row * NN);

    int loc[32];
    int lc = 0;      // stored candidates (capped at 32)
    int cnt = 0;     // true nonzero count for this lane (uncapped)

    #pragma unroll 1
    for (int it = 0; it < 16; it++) {
        const int base = it * 256;
        uint4 v[8];
        #pragma unroll
        for (int u = 0; u < 8; u++)
            v[u] = __ldcs(&arow[base + u * 32 + lane]);   // streaming reads
        unsigned o = 0u;
        #pragma unroll
        for (int u = 0; u < 8; u++)
            o |= (v[u].x | v[u].y | v[u].z | v[u].w);
        if (o) {  // ~6% of 128B lane-blocks contain a nonzero
            #pragma unroll
            for (int u = 0; u < 8; u++) {
                const int c = 4 * (base + u * 32 + lane);
                if (v[u].x) { if (lc < 32) loc[lc++] = c;     cnt++; }
                if (v[u].y) { if (lc < 32) loc[lc++] = c + 1; cnt++; }
                if (v[u].z) { if (lc < 32) loc[lc++] = c + 2; cnt++; }
                if (v[u].w) { if (lc < 32) loc[lc++] = c + 3; cnt++; }
            }
        }
    }
    const int stored = lc;

    // warp-wide exclusive scan of per-lane stored counts (deterministic order)
    const unsigned m = 0xffffffffu;
    int incl = stored;
    #pragma unroll
    for (int d = 1; d < 32; d <<= 1) {
        int nv = __shfl_up_sync(m, incl, d);
        if (lane >= d) incl += nv;
    }
    const int excl = incl - stored;

    // true degree via full reduction
    int deg = cnt;
    #pragma unroll
    for (int d = 16; d > 0; d >>= 1) deg += __shfl_xor_sync(m, deg, d);

    int* __restrict__ nl = d_nbr + (size_t)row * CAPN;
    for (int t = 0; t < stored; t++) {
        const int p = excl + t;
        if (p < CAPN) nl[p] = loc[t];
    }
    if (lane == 31) {
        const int tot = incl;
        d_cnt[row] = tot < CAPN ? tot : CAPN;
    }
    if (lane == 0)
        d_dinv[row] = rsqrtf((float)deg + 1.0f);   // deg includes self loop
}

// ---------------------------------------------------------------------------
// Kernel 2 (x3): XWs[i,j] = dinv[i] * sum_k H[i,k] * W[k,j]
// v2: H tile staged in shared (coalesced float4); W column held in registers.
// Inner loop: LDS(broadcast, vectorizable) + FFMA. Issue-bound ~2us.
// ---------------------------------------------------------------------------
template <int KI, int KO, int TPB>
__global__ __launch_bounds__(TPB) void gemm_scale(const float* __restrict__ H,
                                                  const float* __restrict__ W,
                                                  const float* __restrict__ dinv,
                                                  float* __restrict__ out) {
    constexpr int ROWS = 64;
    constexpr int NR   = TPB / KO;          // rows computed per sweep
    __shared__ float Hs[ROWS * KI];

    const int tid  = threadIdx.x;
    const int row0 = blockIdx.x * ROWS;

    // coalesced float4 stage of the 64-row H tile
    const float4* __restrict__ Hg =
        reinterpret_cast<const float4*>(H + (size_t)row0 * KI);
    for (int i = tid; i < ROWS * KI / 4; i += TPB)
        reinterpret_cast<float4*>(Hs)[i] = Hg[i];

    // this thread's W column -> registers
    const int tx = tid % KO;
    const int ty = tid / KO;
    float wreg[KI];
    #pragma unroll
    for (int k = 0; k < KI; k++) wreg[k] = __ldg(&W[k * KO + tx]);
    __syncthreads();

    for (int r = ty; r < ROWS; r += NR) {
        float acc = 0.f;
        #pragma unroll
        for (int k = 0; k < KI; k++) acc += Hs[r * KI + k] * wreg[k];
        const int row = row0 + r;
        out[(size_t)row * KO + tx] = dinv[row] * acc;
    }
}

// ---------------------------------------------------------------------------
// Kernel 3 (x3): out[i,:] = relu( dinv[i]*(XWs[i,:] + sum_{j in nbr(i)} XWs[j,:]) + b )
// v2: uniform int4 index loads (broadcast), 4-way unroll, dual accumulators.
// Gathers hit the 4 MB XWs table resident in L2.
// ---------------------------------------------------------------------------
template <int KO>
__global__ __launch_bounds__(256) void spmm_relu(const float* __restrict__ XW,
                                                 const float* __restrict__ bias,
                                                 float* __restrict__ out) {
    const int warp = blockIdx.x * 8 + (threadIdx.x >> 5);
    const int lane = threadIdx.x & 31;
    const int row  = warp;

    const float* __restrict__ self = XW + (size_t)row * KO;
    float a0 = self[lane];                    // self-loop (dinv_j folded in XW)
    float c0 = 0.f;
    float a1 = 0.f, c1 = 0.f;
    const bool has1 = (KO > 32) && (lane + 32 < KO);
    if (has1) a1 = self[32 + lane];

    const int n = d_cnt[row];
    const int* __restrict__ nl = d_nbr + (size_t)row * CAPN;

    int k = 0;
    for (; k + 4 <= n; k += 4) {
        const int4 jj = *reinterpret_cast<const int4*>(nl + k);  // uniform broadcast
        const float* __restrict__ p0 = XW + (size_t)jj.x * KO;
        const float* __restrict__ p1 = XW + (size_t)jj.y * KO;
        const float* __restrict__ p2 = XW + (size_t)jj.z * KO;
        const float* __restrict__ p3 = XW + (size_t)jj.w * KO;
        const float x0 = __ldg(&p0[lane]);
        const float x1 = __ldg(&p1[lane]);
        const float x2 = __ldg(&p2[lane]);
        const float x3 = __ldg(&p3[lane]);
        a0 += x0; c0 += x1; a0 += x2; c0 += x3;
        if (has1) {
            const float y0 = __ldg(&p0[32 + lane]);
            const float y1 = __ldg(&p1[32 + lane]);
            const float y2 = __ldg(&p2[32 + lane]);
            const float y3 = __ldg(&p3[32 + lane]);
            a1 += y0; c1 += y1; a1 += y2; c1 += y3;
        }
    }
    for (; k < n; k++) {
        const int j = nl[k];
        const float* __restrict__ p = XW + (size_t)j * KO;
        a0 += __ldg(&p[lane]);
        if (has1) a1 += __ldg(&p[32 + lane]);
    }

    const float di = d_dinv[row];
    out[(size_t)row * KO + lane] = fmaxf(di * (a0 + c0) + bias[lane], 0.f);
    if (has1)
        out[(size_t)row * KO + 32 + lane] =
            fmaxf(di * (a1 + c1) + bias[32 + lane], 0.f);
}

// ---------------------------------------------------------------------------
// Kernel 4: column partial sums of H3 (16384 x 64) -> 128 partials per column
// ---------------------------------------------------------------------------
__global__ void colsum(const float* __restrict__ H, float* __restrict__ part) {
    __shared__ float sh[4][64];
    const int col = threadIdx.x;   // 64
    const int ty  = threadIdx.y;   // 4
    const int row0 = blockIdx.x * 128;
    float s = 0.f;
    for (int r = ty; r < 128; r += 4)
        s += H[(size_t)(row0 + r) * 64 + col];
    sh[ty][col] = s;
    __syncthreads();
    if (ty == 0)
        part[blockIdx.x * 64 + col] = sh[0][col] + sh[1][col] + sh[2][col] + sh[3][col];
}

// ---------------------------------------------------------------------------
// Kernel 5: finish mean, MLP head (elu), logits, softmax. Single block, 64 thr.
// ---------------------------------------------------------------------------
__global__ void head(const float* __restrict__ part,
                     const float* __restrict__ Wh1, const float* __restrict__ bh1,
                     const float* __restrict__ Wh2, const float* __restrict__ bh2,
                     float* __restrict__ out) {
    __shared__ float g[64], h1[32], lg[2];
    const int t = threadIdx.x;  // 64 threads
    float s = 0.f;
    for (int b = 0; b < 128; b++) s += part[b * 64 + t];
    g[t] = s * (1.0f / (float)NN);
    __syncthreads();
    if (t < MLP_H) {
        float a = bh1[t];
        #pragma unroll
        for (int k = 0; k < 64; k++) a += g[k] * Wh1[k * MLP_H + t];
        h1[t] = (a > 0.f) ? a : expm1f(a);   // elu, alpha=1
    }
    __syncthreads();
    if (t < NCLS) {
        float a = bh2[t];
        #pragma unroll
        for (int k = 0; k < MLP_H; k++) a += h1[k] * Wh2[k * NCLS + t];
        lg[t] = a;
        out[t] = a;                          // logits
    }
    __syncthreads();
    if (t == 0) {
        const float mx = fmaxf(lg[0], lg[1]);
        const float e0 = expf(lg[0] - mx), e1 = expf(lg[1] - mx);
        const float inv = 1.f / (e0 + e1);
        out[2] = e0 * inv;                   // probs
        out[3] = e1 * inv;
    }
}

// ---------------------------------------------------------------------------
extern "C" void kernel_launch(void* const* d_in, const int* in_sizes, int n_in,
                              void* d_out, int out_size) {
    const float* nf   = (const float*)d_in[0];   // [N, 64]
    const float* adj  = (const float*)d_in[1];   // [N, N]
    const float* W0   = (const float*)d_in[2];   // [64, 32]
    const float* b0   = (const float*)d_in[3];
    const float* W1   = (const float*)d_in[4];   // [32, 48]
    const float* b1   = (const float*)d_in[5];
    const float* W2   = (const float*)d_in[6];   // [48, 64]
    const float* b2   = (const float*)d_in[7];
    const float* Wh1  = (const float*)d_in[8];   // [64, 32]
    const float* bh1  = (const float*)d_in[9];
    const float* Wh2  = (const float*)d_in[10];  // [32, 2]
    const float* bh2  = (const float*)d_in[11];
    float* out = (float*)d_out;

    float *xw, *hb, *pt, *dinv;
    cudaGetSymbolAddress((void**)&xw,   d_xw);
    cudaGetSymbolAddress((void**)&hb,   d_hb);
    cudaGetSymbolAddress((void**)&pt,   d_part);
    cudaGetSymbolAddress((void**)&dinv, d_dinv);

    // 1) sparse extraction (the 1 GiB streaming pass; HBM-bound)
    build_sparse<<<NN / 8, 256>>>(adj);

    // 2) layer 1: 64 -> 32
    gemm_scale<IN_DIM, L0, 256><<<NN / 64, 256>>>(nf, W0, dinv, xw);
    spmm_relu<L0><<<NN / 8, 256>>>(xw, b0, hb);

    // 3) layer 2: 32 -> 48
    gemm_scale<L0, L1, 192><<<NN / 64, 192>>>(hb, W1, dinv, xw);
    spmm_relu<L1><<<NN / 8, 256>>>(xw, b1, hb);

    // 4) layer 3: 48 -> 64
    gemm_scale<L1, L2, 256><<<NN / 64, 256>>>(hb, W2, dinv, xw);
    spmm_relu<L2><<<NN / 8, 256>>>(xw, b2, hb);

    // 5) mean-pool + MLP + softmax
    colsum<<<128, dim3(64, 4)>>>(hb, pt);
    head<<<1, 64>>>(pt, Wh1, bh1, Wh2, bh2, out);
}

// round 4
// speedup vs baseline: 1.1054x; 1.0131x over previous
#include <cuda_runtime.h>
#include <cstdint>
#include <stddef.h>

// Problem constants (match reference_code)
#define NN      16384
#define IN_DIM  64
#define L0      32
#define L1      48
#define L2      64
#define MLP_H   32
#define NCLS    2
#define CAPN    128   // max neighbors per row (Poisson(~33): P(deg>=128) ~ 1e-30)

// ---------------- scratch (__device__ globals; no allocation allowed) ----------
__device__ int   d_nbr[(size_t)NN * CAPN];   // 8 MB  ELL neighbor indices
__device__ int   d_cnt[NN];
__device__ float d_dinv[NN];
__device__ float d_bufA[(size_t)NN * 64];    // 4 MB  ping
__device__ float d_bufB[(size_t)NN * 64];    // 4 MB  pong
__device__ float d_part[128 * 64];           // column partial sums

// ---------------------------------------------------------------------------
// Kernel 1: stream 1 GiB dense adjacency once; build ELL lists + degrees.
// One warp per row. HBM-bound. __ldcs streams (keeps L2 for gather tables).
// Deterministic: fixed traversal + warp exclusive scan (no atomics).
// ---------------------------------------------------------------------------
__global__ __launch_bounds__(256) void build_sparse(const float* __restrict__ adj) {
    const int warp = blockIdx.x * 8 + (threadIdx.x >> 5);
    const int lane = threadIdx.x & 31;
    const int row  = warp;  // 2048 blocks x 8 warps -> 16384 rows

    const uint4* __restrict__ arow =
        reinterpret_cast<const uint4*>(adj + (size_t)row * NN);

    int loc[32];
    int lc = 0;      // stored candidates (capped at 32)
    int cnt = 0;     // true nonzero count (uncapped)

    #pragma unroll 1
    for (int it = 0; it < 16; it++) {
        const int base = it * 256;
        uint4 v[8];
        #pragma unroll
        for (int u = 0; u < 8; u++)
            v[u] = __ldcs(&arow[base + u * 32 + lane]);
        unsigned o = 0u;
        #pragma unroll
        for (int u = 0; u < 8; u++)
            o |= (v[u].x | v[u].y | v[u].z | v[u].w);
        if (o) {
            #pragma unroll
            for (int u = 0; u < 8; u++) {
                const int c = 4 * (base + u * 32 + lane);
                if (v[u].x) { if (lc < 32) loc[lc++] = c;     cnt++; }
                if (v[u].y) { if (lc < 32) loc[lc++] = c + 1; cnt++; }
                if (v[u].z) { if (lc < 32) loc[lc++] = c + 2; cnt++; }
                if (v[u].w) { if (lc < 32) loc[lc++] = c + 3; cnt++; }
            }
        }
    }
    const int stored = lc;

    const unsigned m = 0xffffffffu;
    int incl = stored;
    #pragma unroll
    for (int d = 1; d < 32; d <<= 1) {
        int nv = __shfl_up_sync(m, incl, d);
        if (lane >= d) incl += nv;
    }
    const int excl = incl - stored;

    int deg = cnt;
    #pragma unroll
    for (int d = 16; d > 0; d >>= 1) deg += __shfl_xor_sync(m, deg, d);

    int* __restrict__ nl = d_nbr + (size_t)row * CAPN;
    for (int t = 0; t < stored; t++) {
        const int p = excl + t;
        if (p < CAPN) nl[p] = loc[t];
    }
    if (lane == 31) {
        const int tot = incl;
        d_cnt[row] = tot < CAPN ? tot : CAPN;
    }
    if (lane == 0)
        d_dinv[row] = rsqrtf((float)deg + 1.0f);   // deg includes self loop
}

// ---------------------------------------------------------------------------
// Kernel 2 (x3): out = epilogue( H @ W )  with H tile in shared.
// v3: 32 rows/block (grid 512), RPT=4 independent accumulators per thread,
// float4 LDS (broadcast within warp), W column in registers.
// MODE 0: out = dinv[row] * acc                      (layer-1 pre-scale)
// MODE 1: out = dinv[row] * relu(acc + bias[tx])     (writes S = dinv.h)
// MODE 2: out = relu(acc + bias[tx])                 (final layer h3)
// ---------------------------------------------------------------------------
template <int KI, int KO, int TPB, int MODE>
__global__ __launch_bounds__(TPB) void gemm_scale(const float* __restrict__ H,
                                                  const float* __restrict__ W,
                                                  const float* __restrict__ dinv,
                                                  const float* __restrict__ bias,
                                                  float* __restrict__ out) {
    constexpr int ROWS = 32;
    constexpr int NR   = TPB / KO;          // rows per sweep
    constexpr int RPT  = ROWS / NR;         // rows per thread (=4)
    __shared__ float Hs[ROWS * KI];

    const int tid  = threadIdx.x;
    const int row0 = blockIdx.x * ROWS;

    const float4* __restrict__ Hg =
        reinterpret_cast<const float4*>(H + (size_t)row0 * KI);
    #pragma unroll
    for (int i = tid; i < ROWS * KI / 4; i += TPB)
        reinterpret_cast<float4*>(Hs)[i] = Hg[i];

    const int tx = tid % KO;
    const int ty = tid / KO;
    float wreg[KI];
    #pragma unroll
    for (int k = 0; k < KI; k++) wreg[k] = __ldg(&W[k * KO + tx]);
    __syncthreads();

    float acc[RPT];
    #pragma unroll
    for (int i = 0; i < RPT; i++) acc[i] = 0.f;

    #pragma unroll
    for (int k4 = 0; k4 < KI / 4; k4++) {
        #pragma unroll
        for (int i = 0; i < RPT; i++) {
            const float4 h =
                *reinterpret_cast<const float4*>(&Hs[(ty + i * NR) * KI + 4 * k4]);
            acc[i] += h.x * wreg[4 * k4 + 0] + h.y * wreg[4 * k4 + 1]
                    + h.z * wreg[4 * k4 + 2] + h.w * wreg[4 * k4 + 3];
        }
    }

    #pragma unroll
    for (int i = 0; i < RPT; i++) {
        const int row = row0 + ty + i * NR;
        float v;
        if (MODE == 0)      v = dinv[row] * acc[i];
        else if (MODE == 1) v = dinv[row] * fmaxf(acc[i] + bias[tx], 0.f);
        else                v = fmaxf(acc[i] + bias[tx], 0.f);
        out[(size_t)row * KO + tx] = v;
    }
}

// ---------------------------------------------------------------------------
// Kernel 3 (x3): gather-aggregate over neighbor lists (L2-resident table).
// sum_i = X[i,:] + sum_{j in nbr(i)} X[j,:]
// MODE 0 (layer-1, X = dinv.(nf@W0)):  out = dinv_i * relu(dinv_i*sum + b)
// MODE 1 (X = S = dinv.h):             out = dinv_i * sum           (= z)
// ---------------------------------------------------------------------------
template <int KO, int MODE>
__global__ __launch_bounds__(256) void spmm_agg(const float* __restrict__ X,
                                                const float* __restrict__ bias,
                                                float* __restrict__ out) {
    const int warp = blockIdx.x * 8 + (threadIdx.x >> 5);
    const int lane = threadIdx.x & 31;
    const int row  = warp;

    const float* __restrict__ self = X + (size_t)row * KO;
    float a0 = self[lane];
    float c0 = 0.f;
    float a1 = 0.f, c1 = 0.f;
    const bool has1 = (KO > 32) && (lane + 32 < KO);
    if (has1) a1 = self[32 + lane];

    const int n = d_cnt[row];
    const int* __restrict__ nl = d_nbr + (size_t)row * CAPN;

    int k = 0;
    for (; k + 4 <= n; k += 4) {
        const int4 jj = *reinterpret_cast<const int4*>(nl + k);  // uniform bcast
        const float* __restrict__ p0 = X + (size_t)jj.x * KO;
        const float* __restrict__ p1 = X + (size_t)jj.y * KO;
        const float* __restrict__ p2 = X + (size_t)jj.z * KO;
        const float* __restrict__ p3 = X + (size_t)jj.w * KO;
        const float x0 = __ldg(&p0[lane]);
        const float x1 = __ldg(&p1[lane]);
        const float x2 = __ldg(&p2[lane]);
        const float x3 = __ldg(&p3[lane]);
        a0 += x0; c0 += x1; a0 += x2; c0 += x3;
        if (has1) {
            const float y0 = __ldg(&p0[32 + lane]);
            const float y1 = __ldg(&p1[32 + lane]);
            const float y2 = __ldg(&p2[32 + lane]);
            const float y3 = __ldg(&p3[32 + lane]);
            a1 += y0; c1 += y1; a1 += y2; c1 += y3;
        }
    }
    for (; k < n; k++) {
        const int j = nl[k];
        const float* __restrict__ p = X + (size_t)j * KO;
        a0 += __ldg(&p[lane]);
        if (has1) a1 += __ldg(&p[32 + lane]);
    }

    const float di = d_dinv[row];
    const float s0 = a0 + c0;
    if (MODE == 0) {
        out[(size_t)row * KO + lane] = di * fmaxf(di * s0 + bias[lane], 0.f);
        if (has1) {
            const float s1 = a1 + c1;
            out[(size_t)row * KO + 32 + lane] =
                di * fmaxf(di * s1 + bias[32 + lane], 0.f);
        }
    } else {
        out[(size_t)row * KO + lane] = di * s0;
        if (has1)
            out[(size_t)row * KO + 32 + lane] = di * (a1 + c1);
    }
}

// ---------------------------------------------------------------------------
// Kernel 4: column partial sums of H3 (16384 x 64) -> 128 partials per column
// ---------------------------------------------------------------------------
__global__ void colsum(const float* __restrict__ H, float* __restrict__ part) {
    __shared__ float sh[4][64];
    const int col = threadIdx.x;   // 64
    const int ty  = threadIdx.y;   // 4
    const int row0 = blockIdx.x * 128;
    float s = 0.f;
    for (int r = ty; r < 128; r += 4)
        s += H[(size_t)(row0 + r) * 64 + col];
    sh[ty][col] = s;
    __syncthreads();
    if (ty == 0)
        part[blockIdx.x * 64 + col] = sh[0][col] + sh[1][col] + sh[2][col] + sh[3][col];
}

// ---------------------------------------------------------------------------
// Kernel 5: finish mean, MLP head (elu), logits, softmax. Single block, 64 thr.
// ---------------------------------------------------------------------------
__global__ void head(const float* __restrict__ part,
                     const float* __restrict__ Wh1, const float* __restrict__ bh1,
                     const float* __restrict__ Wh2, const float* __restrict__ bh2,
                     float* __restrict__ out) {
    __shared__ float g[64], h1[32], lg[2];
    const int t = threadIdx.x;  // 64 threads
    float s = 0.f;
    for (int b = 0; b < 128; b++) s += part[b * 64 + t];
    g[t] = s * (1.0f / (float)NN);
    __syncthreads();
    if (t < MLP_H) {
        float a = bh1[t];
        #pragma unroll
        for (int k = 0; k < 64; k++) a += g[k] * Wh1[k * MLP_H + t];
        h1[t] = (a > 0.f) ? a : expm1f(a);   // elu, alpha=1
    }
    __syncthreads();
    if (t < NCLS) {
        float a = bh2[t];
        #pragma unroll
        for (int k = 0; k < MLP_H; k++) a += h1[k] * Wh2[k * NCLS + t];
        lg[t] = a;
        out[t] = a;                          // logits
    }
    __syncthreads();
    if (t == 0) {
        const float mx = fmaxf(lg[0], lg[1]);
        const float e0 = expf(lg[0] - mx), e1 = expf(lg[1] - mx);
        const float inv = 1.f / (e0 + e1);
        out[2] = e0 * inv;                   // probs
        out[3] = e1 * inv;
    }
}

// ---------------------------------------------------------------------------
extern "C" void kernel_launch(void* const* d_in, const int* in_sizes, int n_in,
                              void* d_out, int out_size) {
    const float* nf   = (const float*)d_in[0];   // [N, 64]
    const float* adj  = (const float*)d_in[1];   // [N, N]
    const float* W0   = (const float*)d_in[2];   // [64, 32]
    const float* b0   = (const float*)d_in[3];
    const float* W1   = (const float*)d_in[4];   // [32, 48]
    const float* b1   = (const float*)d_in[5];
    const float* W2   = (const float*)d_in[6];   // [48, 64]
    const float* b2   = (const float*)d_in[7];
    const float* Wh1  = (const float*)d_in[8];   // [64, 32]
    const float* bh1  = (const float*)d_in[9];
    const float* Wh2  = (const float*)d_in[10];  // [32, 2]
    const float* bh2  = (const float*)d_in[11];
    float* out = (float*)d_out;

    float *bufA, *bufB, *pt, *dinv;
    cudaGetSymbolAddress((void**)&bufA, d_bufA);
    cudaGetSymbolAddress((void**)&bufB, d_bufB);
    cudaGetSymbolAddress((void**)&pt,   d_part);
    cudaGetSymbolAddress((void**)&dinv, d_dinv);

    // 1) sparse extraction (1 GiB streaming pass; HBM-bound)
    build_sparse<<<NN / 8, 256>>>(adj);

    // 2) layer 1 (multiply-first: in 64 > out 32)
    gemm_scale<IN_DIM, L0, 256, 0><<<NN / 32, 256>>>(nf, W0, dinv, nullptr, bufA);
    spmm_agg<L0, 0><<<NN / 8, 256>>>(bufA, b0, bufB);     // bufB = S1 = dinv.h1

    // 3) layer 2 (aggregate-first: gather on width 32, then 32->48 GEMM)
    spmm_agg<L0, 1><<<NN / 8, 256>>>(bufB, nullptr, bufA);               // z2
    gemm_scale<L0, L1, 384, 1><<<NN / 32, 384>>>(bufA, W1, dinv, b1, bufB); // S2

    // 4) layer 3 (aggregate-first: gather on width 48, then 48->64 GEMM)
    spmm_agg<L1, 1><<<NN / 8, 256>>>(bufB, nullptr, bufA);               // z3
    gemm_scale<L1, L2, 512, 2><<<NN / 32, 512>>>(bufA, W2, dinv, b2, bufB); // h3

    // 5) mean-pool + MLP + softmax
    colsum<<<128, dim3(64, 4)>>>(bufB, pt);
    head<<<1, 64>>>(pt, Wh1, bh1, Wh2, bh2, out);
}